// round 14
// baseline (speedup 1.0000x reference)
#include <cuda_runtime.h>
#include <math.h>

#define B 64
#define C0 8
#define HW0 3136
#define HW1 324
#define F 10368
#define EPSN 1e-5f

// ---------------- persistent scratch ----------------
__device__ float g_h0[B*C0*HW0];
__device__ float g_ps0[B*7*16];
__device__ float g_h1[B*16*HW1];
__device__ float g_a1[B*16], g_b1[B*16];
__device__ float g_h2[B*32*HW1];
__device__ float g_a2[B*32], g_b2[B*32];
__device__ float g_part[81*B*32];

// ---------------- packed f32x2 helpers (sm_103a FFMA2 path) ----------------
__device__ __forceinline__ unsigned long long pk2(float lo, float hi) {
    unsigned long long r;
    asm("mov.b64 %0, {%1, %2};" : "=l"(r)
        : "r"(__float_as_uint(lo)), "r"(__float_as_uint(hi)));
    return r;
}
__device__ __forceinline__ void fma2(unsigned long long& d,
                                     unsigned long long a, unsigned long long b) {
    asm("fma.rn.f32x2 %0, %1, %2, %0;" : "+l"(d) : "l"(a), "l"(b));
}
__device__ __forceinline__ float2 upk(unsigned long long p) {
    unsigned int lo, hi;
    asm("mov.b64 {%0, %1}, %2;" : "=r"(lo), "=r"(hi) : "l"(p));
    return make_float2(__uint_as_float(lo), __uint_as_float(hi));
}

// ---------------- K1: conv0 7x7 s4 p2 + per-block GroupNorm partials ----------------
// grid 448 = 64b x 7 tiles, block 224.
__global__ void k_conv0(const float* __restrict__ x, const float* __restrict__ w,
                        const float* __restrict__ bias) {
    extern __shared__ float sm[];
    float* s_in = sm;            // 23940
    float* s_w  = sm + 23940;    // 1176
    __shared__ float s_ps[7][16];
    int blk = blockIdx.x;
    int b = blk / 7, tile = blk - b * 7;
    int tid = threadIdx.x;

    for (int i = tid; i < 1176; i += 224) {
        int o = i / 147, rem = i - o * 147;
        s_w[rem * 8 + o] = w[i];
    }
    for (int i = tid; i < 5985; i += 224)
        ((float4*)s_in)[i] = make_float4(0.f, 0.f, 0.f, 0.f);
    __syncthreads();

    const float* xb = x + (size_t)b * 3 * 224 * 224;
    for (int i = tid; i < 5880; i += 224) {
        int ic = i / 1960;
        int rem = i - ic * 1960;
        int r = rem / 56, cch = rem - r * 56;
        int gr = tile * 32 - 2 + r;
        if (gr >= 0 && gr < 224) {
            float4 v = *(const float4*)(xb + (ic * 224 + gr) * 224 + cch * 4);
            float* base = s_in + ((ic * 35 + r) * 4) * 57;
            base[2 * 57 + cch]     = v.x;
            base[3 * 57 + cch]     = v.y;
            base[0 * 57 + cch + 1] = v.z;
            base[1 * 57 + cch + 1] = v.w;
        }
    }
    __syncthreads();
    cudaTriggerProgrammaticLaunchCompletion();   // let conv1 prestage

    int r0 = tid / 56, ocol = tid - r0 * 56;
    unsigned long long a0[4], a1[4];
#pragma unroll
    for (int o = 0; o < 4; o++) { a0[o] = 0ull; a1[o] = 0ull; }

    for (int ic = 0; ic < 3; ic++)
#pragma unroll
        for (int ky = 0; ky < 7; ky++) {
            int rowbase = (ic * 35 + r0 * 4 + ky) * 4;
            int tap0 = (ic * 49 + ky * 7) * 8;
#pragma unroll
            for (int kx = 0; kx < 7; kx++) {
                int idx = (rowbase + (kx & 3)) * 57 + ocol + (kx >> 2);
                float v0 = s_in[idx];
                float v1 = s_in[idx + 16 * 4 * 57];
                unsigned long long v0p = pk2(v0, v0);
                unsigned long long v1p = pk2(v1, v1);
                const ulonglong2* wq = (const ulonglong2*)(s_w + tap0 + kx * 8);
                ulonglong2 wA = wq[0], wB = wq[1];
                fma2(a0[0], v0p, wA.x); fma2(a0[1], v0p, wA.y);
                fma2(a0[2], v0p, wB.x); fma2(a0[3], v0p, wB.y);
                fma2(a1[0], v1p, wA.x); fma2(a1[1], v1p, wA.y);
                fma2(a1[2], v1p, wB.x); fma2(a1[3], v1p, wB.y);
            }
        }
    int orow0 = tile * 8 + r0;
    float sv[8], sq[8];
#pragma unroll
    for (int o2 = 0; o2 < 4; o2++) {
        float2 p0 = upk(a0[o2]);
        float2 p1 = upk(a1[o2]);
        int o = o2 * 2;
        float bv0 = bias[o], bv1 = bias[o + 1];
        float v00 = p0.x + bv0, v01 = p0.y + bv1;
        float v10 = p1.x + bv0, v11 = p1.y + bv1;
        g_h0[((b * 8 + o) * 56 + orow0) * 56 + ocol]         = v00;
        g_h0[((b * 8 + o + 1) * 56 + orow0) * 56 + ocol]     = v01;
        g_h0[((b * 8 + o) * 56 + orow0 + 4) * 56 + ocol]     = v10;
        g_h0[((b * 8 + o + 1) * 56 + orow0 + 4) * 56 + ocol] = v11;
        sv[o]     = v00 + v10;
        sq[o]     = fmaf(v00, v00, v10 * v10);
        sv[o + 1] = v01 + v11;
        sq[o + 1] = fmaf(v01, v01, v11 * v11);
    }
    int lane = tid & 31, wid = tid >> 5;
#pragma unroll
    for (int o = 0; o < 8; o++) {
        float s = sv[o], q = sq[o];
#pragma unroll
        for (int off = 16; off > 0; off >>= 1) {
            s += __shfl_xor_sync(0xffffffffu, s, off);
            q += __shfl_xor_sync(0xffffffffu, q, off);
        }
        if (lane == 0) { s_ps[wid][o * 2] = s; s_ps[wid][o * 2 + 1] = q; }
    }
    __syncthreads();
    if (tid < 16) {
        float acc = 0.f;
#pragma unroll
        for (int wI = 0; wI < 7; wI++) acc += s_ps[wI][tid];
        g_ps0[(b * 7 + tile) * 16 + tid] = acc;
    }
}

// ---------------- K2: conv1 5x5 s3 p1, (batch, 9-row half, 16 oc), 672 thr ----------------
// grid 128 = 64b x 2 row-halves.
__global__ void __launch_bounds__(672) k_conv1(const float* __restrict__ w,
                                               const float* __restrict__ bias,
                                               const float* __restrict__ gw,
                                               const float* __restrict__ gb) {
    extern __shared__ float sm[];
    float* s_in = sm;            // 12992
    float* s_w  = sm + 12992;    // 3200
    __shared__ float s_a[8], s_b[8];
    int b = blockIdx.x >> 1, rh = blockIdx.x & 1;
    int tid = threadIdx.x;

    // phase A: weight staging (independent of conv0 output)
    for (int i = tid; i < 3200; i += 672) {
        int o = i / 200, rem = i - o * 200;
        s_w[rem * 16 + o] = w[i];
    }
    cudaGridDependencySynchronize();
    cudaTriggerProgrammaticLaunchCompletion();

    if (tid < 8) {
        float S = 0.f, Q = 0.f;
#pragma unroll
        for (int t = 0; t < 7; t++) {
            S += g_ps0[(b * 7 + t) * 16 + tid * 2];
            Q += g_ps0[(b * 7 + t) * 16 + tid * 2 + 1];
        }
        float mu = S * (1.f / 3136.f);
        float var = Q * (1.f / 3136.f) - mu * mu;   // biased
        float a = rsqrtf(var + EPSN) * gw[tid];
        s_a[tid] = a;
        s_b[tid] = gb[tid] - mu * a;
    }
    __syncthreads();

    int rowbase = 27 * rh - 1;
    const float* h0b = g_h0 + (size_t)b * 8 * HW0;
    for (int i = tid; i < 12992; i += 672) {
        int ic = i / 1624;
        int rem = i - ic * 1624;
        int r = rem / 56, cc = rem - r * 56;
        int grow = rowbase + r, gcol = cc - 1;
        float v = 0.f;
        if (grow >= 0 && gcol >= 0)
            v = fmaxf(fmaf(h0b[ic * 3136 + grow * 56 + gcol], s_a[ic], s_b[ic]), 0.f);
        s_in[i] = v;
    }
    __syncthreads();

    if (tid < 648) {
        int pos = tid % 162, ocg = tid / 162;
        int oy_l = pos / 18, ox = pos - oy_l * 18;
        unsigned long long acc[2] = {0ull, 0ull};
        for (int ic = 0; ic < 8; ic++) {
#pragma unroll
            for (int ky = 0; ky < 5; ky++) {
                const float* ip = s_in + (ic * 29 + oy_l * 3 + ky) * 56 + ox * 3;
                float v0 = ip[0], v1 = ip[1], v2 = ip[2], v3 = ip[3], v4 = ip[4];
                const float* wp = s_w + (ic * 25 + ky * 5) * 16 + ocg * 4;
                ulonglong2 w0 = *(const ulonglong2*)(wp);
                ulonglong2 w1 = *(const ulonglong2*)(wp + 16);
                ulonglong2 w2 = *(const ulonglong2*)(wp + 32);
                ulonglong2 w3 = *(const ulonglong2*)(wp + 48);
                ulonglong2 w4 = *(const ulonglong2*)(wp + 64);
                unsigned long long p0 = pk2(v0, v0), p1 = pk2(v1, v1), p2 = pk2(v2, v2);
                unsigned long long p3 = pk2(v3, v3), p4 = pk2(v4, v4);
                fma2(acc[0], p0, w0.x); fma2(acc[1], p0, w0.y);
                fma2(acc[0], p1, w1.x); fma2(acc[1], p1, w1.y);
                fma2(acc[0], p2, w2.x); fma2(acc[1], p2, w2.y);
                fma2(acc[0], p3, w3.x); fma2(acc[1], p3, w3.y);
                fma2(acc[0], p4, w4.x); fma2(acc[1], p4, w4.y);
            }
        }
        int oy_g = rh * 9 + oy_l;
        int gpos = oy_g * 18 + ox;
        int oc = ocg * 4;
        float2 pA = upk(acc[0]), pB = upk(acc[1]);
        g_h1[(b * 16 + oc + 0) * HW1 + gpos] = pA.x + bias[oc + 0];
        g_h1[(b * 16 + oc + 1) * HW1 + gpos] = pA.y + bias[oc + 1];
        g_h1[(b * 16 + oc + 2) * HW1 + gpos] = pB.x + bias[oc + 2];
        g_h1[(b * 16 + oc + 3) * HW1 + gpos] = pB.y + bias[oc + 3];
    }
}

// ---------------- K3/K5: entropy + instance-norm stats per (b,c), 224 thr ----------------
__global__ void __launch_bounds__(224) k_entstats(const float* __restrict__ src,
                                                  float* __restrict__ ga, float* __restrict__ gb,
                                                  const float* __restrict__ nw,
                                                  const float* __restrict__ nb, int Cmask) {
    __shared__ float s_ch[324];
    __shared__ float s_e[26];
    __shared__ float sred[24];
    int bc = blockIdx.x, c = bc & Cmask;
    int tid = threadIdx.x;

    // phase A: LUT (independent)
    if (tid < 26) {
        float pk = __fdiv_rn((float)tid, 25.0f);
        float pc = fminf(fmaxf(pk, 1e-5f), 1.0f - 1e-5f);
        s_e[tid] = -pk * logf(pc);
    }
    cudaGridDependencySynchronize();
    cudaTriggerProgrammaticLaunchCompletion();

    float s = 0.f, q = 0.f;
    if (tid < 81) {
        float4 v4 = ((const float4*)(src + (size_t)bc * 324))[tid];
        ((float4*)s_ch)[tid] = v4;
        s = v4.x + v4.y + v4.z + v4.w;
        q = fmaf(v4.x, v4.x, fmaf(v4.y, v4.y, fmaf(v4.z, v4.z, v4.w * v4.w)));
    }
    __syncthreads();

    float ep = 0.f;
    if (tid < 196) {
        int py = tid / 14, px = tid - py * 14;
        const float* pbase = s_ch + py * 18 + px;
        float v[25];
#pragma unroll
        for (int dy = 0; dy < 5; dy++)
#pragma unroll
            for (int dx = 0; dx < 5; dx++)
                v[dy * 5 + dx] = pbase[dy * 18 + dx];
        float mn8[8], mx8[8];
#pragma unroll
        for (int i = 0; i < 8; i++) {
            float a2 = fminf(v[3 * i], v[3 * i + 1]);
            float b2 = fmaxf(v[3 * i], v[3 * i + 1]);
            mn8[i] = fminf(a2, v[3 * i + 2]);
            mx8[i] = fmaxf(b2, v[3 * i + 2]);
        }
        float mn4a = fminf(fminf(mn8[0], mn8[1]), fminf(mn8[2], mn8[3]));
        float mn4b = fminf(fminf(mn8[4], mn8[5]), fminf(mn8[6], mn8[7]));
        float mx4a = fmaxf(fmaxf(mx8[0], mx8[1]), fmaxf(mx8[2], mx8[3]));
        float mx4b = fmaxf(fmaxf(mx8[4], mx8[5]), fmaxf(mx8[6], mx8[7]));
        float mn = fminf(fminf(mn4a, mn4b), v[24]);
        float mx = fmaxf(fmaxf(mx4a, mx4b), v[24]);

        if (mx == mn) {
            ep = s_e[25];
        } else {
            float rng = mx - mn;
            float s25 = __frcp_rn(rng) * 25.0f;
            float ms  = -mn * s25;
            unsigned long long lo0 = 0ull, lo1 = 0ull, hi0 = 0ull, hi1 = 0ull;
            int c24 = 0;
#pragma unroll
            for (int i = 0; i < 25; i++) {
                float t = fmaf(v[i], s25, ms);
                int bi = (int)t;
                bi = bi > 24 ? 24 : bi;
                unsigned long long inc;
                if (bi < 12) {
                    inc = 1ull << (bi * 5);
                    if (i & 1) lo1 += inc; else lo0 += inc;
                } else if (bi < 24) {
                    inc = 1ull << ((bi - 12) * 5);
                    if (i & 1) hi1 += inc; else hi0 += inc;
                } else c24++;
            }
            unsigned long long lo = lo0 + lo1, hi = hi0 + hi1;
#pragma unroll
            for (int k = 0; k < 12; k++) ep += s_e[(unsigned)(lo >> (k * 5)) & 31u];
#pragma unroll
            for (int k = 0; k < 12; k++) ep += s_e[(unsigned)(hi >> (k * 5)) & 31u];
            ep += s_e[c24];
        }
    }

    int lane = tid & 31, wid = tid >> 5;
#pragma unroll
    for (int o = 16; o > 0; o >>= 1) {
        s  += __shfl_xor_sync(0xffffffffu, s, o);
        q  += __shfl_xor_sync(0xffffffffu, q, o);
        ep += __shfl_xor_sync(0xffffffffu, ep, o);
    }
    if (lane == 0) { sred[wid] = s; sred[wid + 8] = q; sred[wid + 16] = ep; }
    __syncthreads();
    if (tid == 0) {
        float S = 0.f, Q = 0.f, E = 0.f;
        for (int wI = 0; wI < 7; wI++) { S += sred[wI]; Q += sred[wI + 8]; E += sred[wI + 16]; }
        float ent = E * (1.0f / 196.0f);
        float mu = S * (1.0f / 324.0f);
        float var = (Q * (1.0f / 324.0f) - mu * mu) * (324.0f / 323.0f);
        float a = rsqrtf(var + EPSN) * nw[c] * ent;
        ga[bc] = a;
        gb[bc] = nb[c] - mu * a;
    }
}

// ---------------- K4: conv2 3x3 s1 p1, (batch, 9-row half, 32 oc), 672 thr ----------------
// grid 128.
__global__ void __launch_bounds__(672) k_conv2(const float* __restrict__ w,
                                               const float* __restrict__ bias) {
    extern __shared__ float sm[];
    float* s_in = sm;            // 3520
    float* s_w  = sm + 3520;     // 4608
    __shared__ float s_a[16], s_b[16];
    int b = blockIdx.x >> 1, rh = blockIdx.x & 1;
    int tid = threadIdx.x;

    // phase A: weight staging (independent)
    for (int i = tid; i < 4608; i += 672) {
        int o = i / 144, rem = i - o * 144;
        s_w[rem * 32 + o] = w[i];
    }
    cudaGridDependencySynchronize();
    cudaTriggerProgrammaticLaunchCompletion();

    if (tid < 16) { s_a[tid] = g_a1[b * 16 + tid]; s_b[tid] = g_b1[b * 16 + tid]; }
    __syncthreads();

    int rowbase = rh * 9 - 1;
    for (int i = tid; i < 3520; i += 672) {
        int ic = i / 220;
        int rem = i - ic * 220;
        int r = rem / 20, cc = rem - r * 20;
        int grow = rowbase + r, gcol = cc - 1;
        float v = 0.f;
        if (grow >= 0 && grow < 18 && gcol >= 0 && gcol < 18)
            v = fmaxf(fmaf(g_h1[(b * 16 + ic) * 324 + grow * 18 + gcol], s_a[ic], s_b[ic]), 0.f);
        s_in[i] = v;
    }
    __syncthreads();

    if (tid < 648) {
        int pos = tid % 162, ocg = tid / 162;
        int oy_l = pos / 18, ox = pos - oy_l * 18;
        unsigned long long acc[4] = {0ull, 0ull, 0ull, 0ull};
        for (int ic = 0; ic < 16; ic++) {
            const float* rp = s_in + (ic * 11 + oy_l) * 20 + ox;
            float i00 = rp[0],  i01 = rp[1],  i02 = rp[2];
            float i10 = rp[20], i11 = rp[21], i12 = rp[22];
            float i20 = rp[40], i21 = rp[41], i22 = rp[42];
            const float* wp = s_w + ic * 9 * 32 + ocg * 8;
            float iv[9] = {i00, i01, i02, i10, i11, i12, i20, i21, i22};
#pragma unroll
            for (int t = 0; t < 9; t++) {
                unsigned long long vp = pk2(iv[t], iv[t]);
                const ulonglong2* wq = (const ulonglong2*)(wp + t * 32);
                ulonglong2 w0 = wq[0], w1 = wq[1];
                fma2(acc[0], vp, w0.x); fma2(acc[1], vp, w0.y);
                fma2(acc[2], vp, w1.x); fma2(acc[3], vp, w1.y);
            }
        }
        int oy_g = rh * 9 + oy_l;
        int gpos = oy_g * 18 + ox;
        int oc = ocg * 8;
#pragma unroll
        for (int o2 = 0; o2 < 4; o2++) {
            float2 p = upk(acc[o2]);
            g_h2[(b * 32 + oc + o2 * 2) * HW1 + gpos]     = p.x + bias[oc + o2 * 2];
            g_h2[(b * 32 + oc + o2 * 2 + 1) * HW1 + gpos] = p.y + bias[oc + o2 * 2 + 1];
        }
    }
}

// ---------------- K6: fused BN1d + split-K GEMM ----------------
__global__ void k_gemm(const float* __restrict__ fw, const float* __restrict__ bng,
                       const float* __restrict__ bnb) {
    extern __shared__ float sm[];
    float* s_h  = sm;                 // 64 x 132
    float* s_w  = sm + 64 * 132;      // 32 x 128
    float* s_rs = s_w + 4096;
    float* s_rq = s_rs + 256;
    float* s_sc = s_rq + 256;
    float* s_sh = s_sc + 128;
    int f0 = blockIdx.x * 128;
    int tid = threadIdx.x;

    // phase A: weight staging (16KB from fc1_w, independent of conv outputs)
    for (int i = tid; i < 1024; i += 256) {
        int jrow = i >> 5, k4 = i & 31;
        float4 v = *(const float4*)(fw + (size_t)jrow * F + f0 + k4 * 4);
        *(float4*)(s_w + jrow * 128 + k4 * 4) = v;
    }
    cudaGridDependencySynchronize();
    cudaTriggerProgrammaticLaunchCompletion();

    for (int i = tid; i < 8192; i += 256) {
        int bb = i >> 7, k = i & 127;
        int f = f0 + k, c = f / 324;
        s_h[bb * 132 + k] =
            fmaxf(fmaf(g_h2[(size_t)bb * F + f], g_a2[bb * 32 + c], g_b2[bb * 32 + c]), 0.f);
    }
    __syncthreads();

    {
        int k = tid & 127, half = tid >> 7;
        float s = 0.f, q = 0.f;
#pragma unroll 8
        for (int bb = half * 32; bb < half * 32 + 32; bb++) {
            float v = s_h[bb * 132 + k];
            s += v; q = fmaf(v, v, q);
        }
        s_rs[tid] = s; s_rq[tid] = q;
    }
    __syncthreads();
    if (tid < 128) {
        float S = s_rs[tid] + s_rs[tid + 128];
        float Q = s_rq[tid] + s_rq[tid + 128];
        float mu = S * (1.f / 64.f);
        float var = Q * (1.f / 64.f) - mu * mu;     // biased
        float sc = bng[f0 + tid] * rsqrtf(var + EPSN);
        s_sc[tid] = sc;
        s_sh[tid] = bnb[f0 + tid] - mu * sc;
    }
    __syncthreads();
    for (int i = tid; i < 8192; i += 256) {
        int bb = i >> 7, k = i & 127;
        s_h[bb * 132 + k] = fmaf(s_h[bb * 132 + k], s_sc[k], s_sh[k]);
    }
    __syncthreads();

    int bb = tid & 63, jg = tid >> 6;
    unsigned long long acc2[8];
#pragma unroll
    for (int j = 0; j < 8; j++) acc2[j] = 0ull;
    const float* hp = s_h + bb * 132;
    const float* wp = s_w + jg * 8 * 128;
    for (int k = 0; k < 128; k += 4) {
        ulonglong2 h2 = *(const ulonglong2*)(hp + k);
#pragma unroll
        for (int j = 0; j < 8; j++) {
            ulonglong2 w2 = *(const ulonglong2*)(wp + j * 128 + k);
            fma2(acc2[j], h2.x, w2.x);
            fma2(acc2[j], h2.y, w2.y);
        }
    }
#pragma unroll
    for (int j = 0; j < 8; j++) {
        float2 p = upk(acc2[j]);
        g_part[(size_t)blockIdx.x * 2048 + bb * 32 + jg * 8 + j] = p.x + p.y;
    }
}

// ---------------- K7: reduce partials (float4) + fc relu + heads + softmax ----------------
__global__ void k_heads(const float* __restrict__ fcb,
                        const float* __restrict__ sw, const float* __restrict__ sb,
                        const float* __restrict__ vw, const float* __restrict__ vb,
                        float* __restrict__ out) {
    __shared__ float s_y[2048];
    int tid = threadIdx.x;
    cudaGridDependencySynchronize();
    if (tid < 512) {
        float4 acc = make_float4(0.f, 0.f, 0.f, 0.f);
#pragma unroll 8
        for (int p = 0; p < 81; p++) {
            float4 v = ((const float4*)(g_part + (size_t)p * 2048))[tid];
            acc.x += v.x; acc.y += v.y; acc.z += v.z; acc.w += v.w;
        }
        int t = tid * 4;
        s_y[t + 0] = fmaxf(acc.x + fcb[t & 31], 0.f);
        s_y[t + 1] = fmaxf(acc.y + fcb[(t + 1) & 31], 0.f);
        s_y[t + 2] = fmaxf(acc.z + fcb[(t + 2) & 31], 0.f);
        s_y[t + 3] = fmaxf(acc.w + fcb[(t + 3) & 31], 0.f);
    }
    __syncthreads();
    if (tid < 64) {
        int b = tid;
        float h[32];
#pragma unroll
        for (int j = 0; j < 32; j++) h[j] = s_y[b * 32 + j];

        float sl[5];
#pragma unroll
        for (int k = 0; k < 5; k++) {
            float a = sb[k];
            for (int j = 0; j < 32; j++) a = fmaf(h[j], sw[k * 32 + j], a);
            sl[k] = a;
        }
        float mx = sl[0];
#pragma unroll
        for (int k = 1; k < 5; k++) mx = fmaxf(mx, sl[k]);
        float den = 0.f;
#pragma unroll
        for (int k = 0; k < 5; k++) { sl[k] = expf(sl[k] - mx); den += sl[k]; }
        float invd = 1.f / den;
#pragma unroll
        for (int k = 0; k < 5; k++) out[b * 5 + k] = sl[k] * invd;

        float vl[2];
#pragma unroll
        for (int k = 0; k < 2; k++) {
            float a = vb[k];
            for (int j = 0; j < 32; j++) a = fmaf(h[j], vw[k * 32 + j], a);
            vl[k] = a;
        }
        float m2 = fmaxf(vl[0], vl[1]);
        float e0 = expf(vl[0] - m2), e1 = expf(vl[1] - m2);
        float id = 1.f / (e0 + e1);
        out[320 + b * 2 + 0] = e0 * id;
        out[320 + b * 2 + 1] = e1 * id;
    }
}

extern "C" void kernel_launch(void* const* d_in, const int* in_sizes, int n_in,
                              void* d_out, int out_size) {
    const float* x       = (const float*)d_in[0];
    const float* conv0_w = (const float*)d_in[1];
    const float* conv0_b = (const float*)d_in[2];
    const float* conv1_w = (const float*)d_in[3];
    const float* conv1_b = (const float*)d_in[4];
    const float* conv2_w = (const float*)d_in[5];
    const float* conv2_b = (const float*)d_in[6];
    const float* gn0_w   = (const float*)d_in[7];
    const float* gn0_b   = (const float*)d_in[8];
    const float* n1_w    = (const float*)d_in[9];
    const float* n1_b    = (const float*)d_in[10];
    const float* n2_w    = (const float*)d_in[11];
    const float* n2_b    = (const float*)d_in[12];
    const float* bn_g    = (const float*)d_in[13];
    const float* bn_b    = (const float*)d_in[14];
    const float* fc1_w   = (const float*)d_in[15];
    const float* fc1_b   = (const float*)d_in[16];
    const float* shape_w = (const float*)d_in[17];
    const float* shape_b = (const float*)d_in[18];
    const float* vern_w  = (const float*)d_in[19];
    const float* vern_b  = (const float*)d_in[20];
    float* out = (float*)d_out;

    float* h1_p; cudaGetSymbolAddress((void**)&h1_p, g_h1);
    float* h2_p; cudaGetSymbolAddress((void**)&h2_p, g_h2);
    float* a1_p; cudaGetSymbolAddress((void**)&a1_p, g_a1);
    float* b1_p; cudaGetSymbolAddress((void**)&b1_p, g_b1);
    float* a2_p; cudaGetSymbolAddress((void**)&a2_p, g_a2);
    float* b2_p; cudaGetSymbolAddress((void**)&b2_p, g_b2);

    const int smem0 = (23940 + 1176) * 4;
    const int smem1 = (12992 + 3200) * 4;
    const int smem2 = (3520 + 4608) * 4;
    const int smemg = (64 * 132 + 4096 + 256 + 256 + 128 + 128) * 4;
    cudaFuncSetAttribute(k_conv0, cudaFuncAttributeMaxDynamicSharedMemorySize, smem0);
    cudaFuncSetAttribute(k_conv1, cudaFuncAttributeMaxDynamicSharedMemorySize, smem1);
    cudaFuncSetAttribute(k_conv2, cudaFuncAttributeMaxDynamicSharedMemorySize, smem2);
    cudaFuncSetAttribute(k_gemm,  cudaFuncAttributeMaxDynamicSharedMemorySize, smemg);

    // PDL launch config (no allocations; graph-capturable)
    cudaLaunchAttribute pdlAttr;
    pdlAttr.id = cudaLaunchAttributeProgrammaticStreamSerialization;
    pdlAttr.val.programmaticStreamSerializationAllowed = 1;

    k_conv0<<<64 * 7, 224, smem0>>>(x, conv0_w, conv0_b);

    {
        cudaLaunchConfig_t cfg = {};
        cfg.gridDim = dim3(128); cfg.blockDim = dim3(672);
        cfg.dynamicSmemBytes = smem1; cfg.stream = 0;
        cfg.attrs = &pdlAttr; cfg.numAttrs = 1;
        cudaLaunchKernelEx(&cfg, k_conv1, conv1_w, conv1_b, gn0_w, gn0_b);
    }
    {
        cudaLaunchConfig_t cfg = {};
        cfg.gridDim = dim3(1024); cfg.blockDim = dim3(224);
        cfg.dynamicSmemBytes = 0; cfg.stream = 0;
        cfg.attrs = &pdlAttr; cfg.numAttrs = 1;
        cudaLaunchKernelEx(&cfg, k_entstats, (const float*)h1_p, a1_p, b1_p, n1_w, n1_b, 15);
    }
    {
        cudaLaunchConfig_t cfg = {};
        cfg.gridDim = dim3(128); cfg.blockDim = dim3(672);
        cfg.dynamicSmemBytes = smem2; cfg.stream = 0;
        cfg.attrs = &pdlAttr; cfg.numAttrs = 1;
        cudaLaunchKernelEx(&cfg, k_conv2, conv2_w, conv2_b);
    }
    {
        cudaLaunchConfig_t cfg = {};
        cfg.gridDim = dim3(2048); cfg.blockDim = dim3(224);
        cfg.dynamicSmemBytes = 0; cfg.stream = 0;
        cfg.attrs = &pdlAttr; cfg.numAttrs = 1;
        cudaLaunchKernelEx(&cfg, k_entstats, (const float*)h2_p, a2_p, b2_p, n2_w, n2_b, 31);
    }
    {
        cudaLaunchConfig_t cfg = {};
        cfg.gridDim = dim3(81); cfg.blockDim = dim3(256);
        cfg.dynamicSmemBytes = smemg; cfg.stream = 0;
        cfg.attrs = &pdlAttr; cfg.numAttrs = 1;
        cudaLaunchKernelEx(&cfg, k_gemm, fc1_w, bn_g, bn_b);
    }
    {
        cudaLaunchConfig_t cfg = {};
        cfg.gridDim = dim3(1); cfg.blockDim = dim3(1024);
        cfg.dynamicSmemBytes = 0; cfg.stream = 0;
        cfg.attrs = &pdlAttr; cfg.numAttrs = 1;
        cudaLaunchKernelEx(&cfg, k_heads, fc1_b, shape_w, shape_b, vern_w, vern_b, out);
    }
}

// round 15
// speedup vs baseline: 1.2529x; 1.2529x over previous
#include <cuda_runtime.h>
#include <math.h>

#define B 64
#define C0 8
#define HW0 3136
#define HW1 324
#define F 10368
#define EPSN 1e-5f

// ---------------- persistent scratch ----------------
__device__ float g_h0[B*C0*HW0];
__device__ float g_ps0[B*7*16];
__device__ float g_h1[B*16*HW1];
__device__ float g_a1[B*16], g_b1[B*16];
__device__ float g_h2[B*32*HW1];
__device__ float g_a2[B*32], g_b2[B*32];
__device__ float g_part[81*B*32];

// ---------------- packed f32x2 helpers (sm_103a FFMA2 path) ----------------
__device__ __forceinline__ unsigned long long pk2(float lo, float hi) {
    unsigned long long r;
    asm("mov.b64 %0, {%1, %2};" : "=l"(r)
        : "r"(__float_as_uint(lo)), "r"(__float_as_uint(hi)));
    return r;
}
__device__ __forceinline__ void fma2(unsigned long long& d,
                                     unsigned long long a, unsigned long long b) {
    asm("fma.rn.f32x2 %0, %1, %2, %0;" : "+l"(d) : "l"(a), "l"(b));
}
__device__ __forceinline__ float2 upk(unsigned long long p) {
    unsigned int lo, hi;
    asm("mov.b64 {%0, %1}, %2;" : "=r"(lo), "=r"(hi) : "l"(p));
    return make_float2(__uint_as_float(lo), __uint_as_float(hi));
}

// ---------------- K1: conv0 7x7 s4 p2 + per-block GroupNorm partials ----------------
// grid 448 = 64b x 7 tiles, block 224.
__global__ void k_conv0(const float* __restrict__ x, const float* __restrict__ w,
                        const float* __restrict__ bias) {
    extern __shared__ float sm[];
    float* s_in = sm;            // 23940
    float* s_w  = sm + 23940;    // 1176
    __shared__ float s_ps[7][16];
    int blk = blockIdx.x;
    int b = blk / 7, tile = blk - b * 7;
    int tid = threadIdx.x;

    for (int i = tid; i < 1176; i += 224) {
        int o = i / 147, rem = i - o * 147;
        s_w[rem * 8 + o] = w[i];
    }
    for (int i = tid; i < 5985; i += 224)
        ((float4*)s_in)[i] = make_float4(0.f, 0.f, 0.f, 0.f);
    __syncthreads();

    const float* xb = x + (size_t)b * 3 * 224 * 224;
    for (int i = tid; i < 5880; i += 224) {
        int ic = i / 1960;
        int rem = i - ic * 1960;
        int r = rem / 56, cch = rem - r * 56;
        int gr = tile * 32 - 2 + r;
        if (gr >= 0 && gr < 224) {
            float4 v = *(const float4*)(xb + (ic * 224 + gr) * 224 + cch * 4);
            float* base = s_in + ((ic * 35 + r) * 4) * 57;
            base[2 * 57 + cch]     = v.x;
            base[3 * 57 + cch]     = v.y;
            base[0 * 57 + cch + 1] = v.z;
            base[1 * 57 + cch + 1] = v.w;
        }
    }
    __syncthreads();

    int r0 = tid / 56, ocol = tid - r0 * 56;
    unsigned long long a0[4], a1[4];
#pragma unroll
    for (int o = 0; o < 4; o++) { a0[o] = 0ull; a1[o] = 0ull; }

    for (int ic = 0; ic < 3; ic++)
#pragma unroll
        for (int ky = 0; ky < 7; ky++) {
            int rowbase = (ic * 35 + r0 * 4 + ky) * 4;
            int tap0 = (ic * 49 + ky * 7) * 8;
#pragma unroll
            for (int kx = 0; kx < 7; kx++) {
                int idx = (rowbase + (kx & 3)) * 57 + ocol + (kx >> 2);
                float v0 = s_in[idx];
                float v1 = s_in[idx + 16 * 4 * 57];
                unsigned long long v0p = pk2(v0, v0);
                unsigned long long v1p = pk2(v1, v1);
                const ulonglong2* wq = (const ulonglong2*)(s_w + tap0 + kx * 8);
                ulonglong2 wA = wq[0], wB = wq[1];
                fma2(a0[0], v0p, wA.x); fma2(a0[1], v0p, wA.y);
                fma2(a0[2], v0p, wB.x); fma2(a0[3], v0p, wB.y);
                fma2(a1[0], v1p, wA.x); fma2(a1[1], v1p, wA.y);
                fma2(a1[2], v1p, wB.x); fma2(a1[3], v1p, wB.y);
            }
        }
    int orow0 = tile * 8 + r0;
    float sv[8], sq[8];
#pragma unroll
    for (int o2 = 0; o2 < 4; o2++) {
        float2 p0 = upk(a0[o2]);
        float2 p1 = upk(a1[o2]);
        int o = o2 * 2;
        float bv0 = bias[o], bv1 = bias[o + 1];
        float v00 = p0.x + bv0, v01 = p0.y + bv1;
        float v10 = p1.x + bv0, v11 = p1.y + bv1;
        g_h0[((b * 8 + o) * 56 + orow0) * 56 + ocol]         = v00;
        g_h0[((b * 8 + o + 1) * 56 + orow0) * 56 + ocol]     = v01;
        g_h0[((b * 8 + o) * 56 + orow0 + 4) * 56 + ocol]     = v10;
        g_h0[((b * 8 + o + 1) * 56 + orow0 + 4) * 56 + ocol] = v11;
        sv[o]     = v00 + v10;
        sq[o]     = fmaf(v00, v00, v10 * v10);
        sv[o + 1] = v01 + v11;
        sq[o + 1] = fmaf(v01, v01, v11 * v11);
    }
    int lane = tid & 31, wid = tid >> 5;
#pragma unroll
    for (int o = 0; o < 8; o++) {
        float s = sv[o], q = sq[o];
#pragma unroll
        for (int off = 16; off > 0; off >>= 1) {
            s += __shfl_xor_sync(0xffffffffu, s, off);
            q += __shfl_xor_sync(0xffffffffu, q, off);
        }
        if (lane == 0) { s_ps[wid][o * 2] = s; s_ps[wid][o * 2 + 1] = q; }
    }
    __syncthreads();
    if (tid < 16) {
        float acc = 0.f;
#pragma unroll
        for (int wI = 0; wI < 7; wI++) acc += s_ps[wI][tid];
        g_ps0[(b * 7 + tile) * 16 + tid] = acc;
    }
}

// ---------------- K2: conv1 5x5 s3 p1, (batch, 9-row half, 16 oc), 672 thr ----------------
__global__ void __launch_bounds__(672) k_conv1(const float* __restrict__ w,
                                               const float* __restrict__ bias,
                                               const float* __restrict__ gw,
                                               const float* __restrict__ gb) {
    extern __shared__ float sm[];
    float* s_in = sm;            // 12992
    float* s_w  = sm + 12992;    // 3200
    __shared__ float s_a[8], s_b[8];
    int b = blockIdx.x >> 1, rh = blockIdx.x & 1;
    int tid = threadIdx.x;

    for (int i = tid; i < 3200; i += 672) {
        int o = i / 200, rem = i - o * 200;
        s_w[rem * 16 + o] = w[i];
    }
    if (tid < 8) {
        float S = 0.f, Q = 0.f;
#pragma unroll
        for (int t = 0; t < 7; t++) {
            S += g_ps0[(b * 7 + t) * 16 + tid * 2];
            Q += g_ps0[(b * 7 + t) * 16 + tid * 2 + 1];
        }
        float mu = S * (1.f / 3136.f);
        float var = Q * (1.f / 3136.f) - mu * mu;   // biased
        float a = rsqrtf(var + EPSN) * gw[tid];
        s_a[tid] = a;
        s_b[tid] = gb[tid] - mu * a;
    }
    __syncthreads();

    int rowbase = 27 * rh - 1;
    const float* h0b = g_h0 + (size_t)b * 8 * HW0;
    for (int i = tid; i < 12992; i += 672) {
        int ic = i / 1624;
        int rem = i - ic * 1624;
        int r = rem / 56, cc = rem - r * 56;
        int grow = rowbase + r, gcol = cc - 1;
        float v = 0.f;
        if (grow >= 0 && gcol >= 0)
            v = fmaxf(fmaf(h0b[ic * 3136 + grow * 56 + gcol], s_a[ic], s_b[ic]), 0.f);
        s_in[i] = v;
    }
    __syncthreads();

    if (tid < 648) {
        int pos = tid % 162, ocg = tid / 162;
        int oy_l = pos / 18, ox = pos - oy_l * 18;
        unsigned long long acc[2] = {0ull, 0ull};
        for (int ic = 0; ic < 8; ic++) {
#pragma unroll
            for (int ky = 0; ky < 5; ky++) {
                const float* ip = s_in + (ic * 29 + oy_l * 3 + ky) * 56 + ox * 3;
                float v0 = ip[0], v1 = ip[1], v2 = ip[2], v3 = ip[3], v4 = ip[4];
                const float* wp = s_w + (ic * 25 + ky * 5) * 16 + ocg * 4;
                ulonglong2 w0 = *(const ulonglong2*)(wp);
                ulonglong2 w1 = *(const ulonglong2*)(wp + 16);
                ulonglong2 w2 = *(const ulonglong2*)(wp + 32);
                ulonglong2 w3 = *(const ulonglong2*)(wp + 48);
                ulonglong2 w4 = *(const ulonglong2*)(wp + 64);
                unsigned long long p0 = pk2(v0, v0), p1 = pk2(v1, v1), p2 = pk2(v2, v2);
                unsigned long long p3 = pk2(v3, v3), p4 = pk2(v4, v4);
                fma2(acc[0], p0, w0.x); fma2(acc[1], p0, w0.y);
                fma2(acc[0], p1, w1.x); fma2(acc[1], p1, w1.y);
                fma2(acc[0], p2, w2.x); fma2(acc[1], p2, w2.y);
                fma2(acc[0], p3, w3.x); fma2(acc[1], p3, w3.y);
                fma2(acc[0], p4, w4.x); fma2(acc[1], p4, w4.y);
            }
        }
        int oy_g = rh * 9 + oy_l;
        int gpos = oy_g * 18 + ox;
        int oc = ocg * 4;
        float2 pA = upk(acc[0]), pB = upk(acc[1]);
        g_h1[(b * 16 + oc + 0) * HW1 + gpos] = pA.x + bias[oc + 0];
        g_h1[(b * 16 + oc + 1) * HW1 + gpos] = pA.y + bias[oc + 1];
        g_h1[(b * 16 + oc + 2) * HW1 + gpos] = pB.x + bias[oc + 2];
        g_h1[(b * 16 + oc + 3) * HW1 + gpos] = pB.y + bias[oc + 3];
    }
}

// ---------------- K3/K5: entropy + instance-norm stats per (b,c), 224 thr ----------------
// register LUT + shfl lookups (conflict-free decode)
__global__ void __launch_bounds__(224) k_entstats(const float* __restrict__ src,
                                                  float* __restrict__ ga, float* __restrict__ gb,
                                                  const float* __restrict__ nw,
                                                  const float* __restrict__ nb, int Cmask) {
    __shared__ float s_ch[324];
    __shared__ float sred[24];
    int bc = blockIdx.x, c = bc & Cmask;
    int tid = threadIdx.x;
    int lane = tid & 31, wid = tid >> 5;

    // register LUT: lane i of every warp holds s_e[i] (i<26)
    float lutv = 0.f;
    {
        int li = lane < 26 ? lane : 25;
        float pk = __fdiv_rn((float)li, 25.0f);
        float pc = fminf(fmaxf(pk, 1e-5f), 1.0f - 1e-5f);
        lutv = -pk * logf(pc);
    }

    float s = 0.f, q = 0.f;
    if (tid < 81) {
        float4 v4 = ((const float4*)(src + (size_t)bc * 324))[tid];
        ((float4*)s_ch)[tid] = v4;
        s = v4.x + v4.y + v4.z + v4.w;
        q = fmaf(v4.x, v4.x, fmaf(v4.y, v4.y, fmaf(v4.z, v4.z, v4.w * v4.w)));
    }
    __syncthreads();

    // all 224 threads run the patch path (full warps -> legal full-mask shfl);
    // threads >=196 compute a duplicate patch and zero their contribution.
    float ep;
    {
        int pidx = tid < 196 ? tid : 195;
        int py = pidx / 14, px = pidx - py * 14;
        const float* pbase = s_ch + py * 18 + px;
        float v[25];
#pragma unroll
        for (int dy = 0; dy < 5; dy++)
#pragma unroll
            for (int dx = 0; dx < 5; dx++)
                v[dy * 5 + dx] = pbase[dy * 18 + dx];
        float mn8[8], mx8[8];
#pragma unroll
        for (int i = 0; i < 8; i++) {
            float a2 = fminf(v[3 * i], v[3 * i + 1]);
            float b2 = fmaxf(v[3 * i], v[3 * i + 1]);
            mn8[i] = fminf(a2, v[3 * i + 2]);
            mx8[i] = fmaxf(b2, v[3 * i + 2]);
        }
        float mn4a = fminf(fminf(mn8[0], mn8[1]), fminf(mn8[2], mn8[3]));
        float mn4b = fminf(fminf(mn8[4], mn8[5]), fminf(mn8[6], mn8[7]));
        float mx4a = fmaxf(fmaxf(mx8[0], mx8[1]), fmaxf(mx8[2], mx8[3]));
        float mx4b = fmaxf(fmaxf(mx8[4], mx8[5]), fmaxf(mx8[6], mx8[7]));
        float mn = fminf(fminf(mn4a, mn4b), v[24]);
        float mx = fmaxf(fmaxf(mx4a, mx4b), v[24]);

        float rng = (mx > mn) ? (mx - mn) : 1.0f;
        float s25 = __frcp_rn(rng) * 25.0f;
        float ms  = -mn * s25;
        unsigned long long lo0 = 0ull, lo1 = 0ull, hi0 = 0ull, hi1 = 0ull;
        int c24 = 0;
#pragma unroll
        for (int i = 0; i < 25; i++) {
            float t = fmaf(v[i], s25, ms);
            int bi = (int)t;
            bi = bi > 24 ? 24 : bi;
            unsigned long long inc;
            if (bi < 12) {
                inc = 1ull << (bi * 5);
                if (i & 1) lo1 += inc; else lo0 += inc;
            } else if (bi < 24) {
                inc = 1ull << ((bi - 12) * 5);
                if (i & 1) hi1 += inc; else hi0 += inc;
            } else c24++;
        }
        unsigned long long lo = lo0 + lo1, hi = hi0 + hi1;
        ep = 0.f;
#pragma unroll
        for (int k = 0; k < 12; k++) {
            int idx = (int)((lo >> (k * 5)) & 31u);
            ep += __shfl_sync(0xffffffffu, lutv, idx);
        }
#pragma unroll
        for (int k = 0; k < 12; k++) {
            int idx = (int)((hi >> (k * 5)) & 31u);
            ep += __shfl_sync(0xffffffffu, lutv, idx);
        }
        ep += __shfl_sync(0xffffffffu, lutv, c24);
        if (tid >= 196) ep = 0.f;
    }

#pragma unroll
    for (int o = 16; o > 0; o >>= 1) {
        s  += __shfl_xor_sync(0xffffffffu, s, o);
        q  += __shfl_xor_sync(0xffffffffu, q, o);
        ep += __shfl_xor_sync(0xffffffffu, ep, o);
    }
    if (lane == 0) { sred[wid] = s; sred[wid + 8] = q; sred[wid + 16] = ep; }
    __syncthreads();
    if (tid == 0) {
        float S = 0.f, Q = 0.f, E = 0.f;
        for (int wI = 0; wI < 7; wI++) { S += sred[wI]; Q += sred[wI + 8]; E += sred[wI + 16]; }
        float ent = E * (1.0f / 196.0f);
        float mu = S * (1.0f / 324.0f);
        float var = (Q * (1.0f / 324.0f) - mu * mu) * (324.0f / 323.0f);
        float a = rsqrtf(var + EPSN) * nw[c] * ent;
        ga[bc] = a;
        gb[bc] = nb[c] - mu * a;
    }
}

// ---------------- K4: conv2 3x3 s1 p1, (batch, 9-row half, 32 oc), 672 thr ----------------
__global__ void __launch_bounds__(672) k_conv2(const float* __restrict__ w,
                                               const float* __restrict__ bias) {
    extern __shared__ float sm[];
    float* s_in = sm;            // 3520
    float* s_w  = sm + 3520;     // 4608
    __shared__ float s_a[16], s_b[16];
    int b = blockIdx.x >> 1, rh = blockIdx.x & 1;
    int tid = threadIdx.x;

    if (tid < 16) { s_a[tid] = g_a1[b * 16 + tid]; s_b[tid] = g_b1[b * 16 + tid]; }
    for (int i = tid; i < 4608; i += 672) {
        int o = i / 144, rem = i - o * 144;
        s_w[rem * 32 + o] = w[i];
    }
    __syncthreads();

    int rowbase = rh * 9 - 1;
    for (int i = tid; i < 3520; i += 672) {
        int ic = i / 220;
        int rem = i - ic * 220;
        int r = rem / 20, cc = rem - r * 20;
        int grow = rowbase + r, gcol = cc - 1;
        float v = 0.f;
        if (grow >= 0 && grow < 18 && gcol >= 0 && gcol < 18)
            v = fmaxf(fmaf(g_h1[(b * 16 + ic) * 324 + grow * 18 + gcol], s_a[ic], s_b[ic]), 0.f);
        s_in[i] = v;
    }
    __syncthreads();

    if (tid < 648) {
        int pos = tid % 162, ocg = tid / 162;
        int oy_l = pos / 18, ox = pos - oy_l * 18;
        unsigned long long acc[4] = {0ull, 0ull, 0ull, 0ull};
        for (int ic = 0; ic < 16; ic++) {
            const float* rp = s_in + (ic * 11 + oy_l) * 20 + ox;
            float i00 = rp[0],  i01 = rp[1],  i02 = rp[2];
            float i10 = rp[20], i11 = rp[21], i12 = rp[22];
            float i20 = rp[40], i21 = rp[41], i22 = rp[42];
            const float* wp = s_w + ic * 9 * 32 + ocg * 8;
            float iv[9] = {i00, i01, i02, i10, i11, i12, i20, i21, i22};
#pragma unroll
            for (int t = 0; t < 9; t++) {
                unsigned long long vp = pk2(iv[t], iv[t]);
                const ulonglong2* wq = (const ulonglong2*)(wp + t * 32);
                ulonglong2 w0 = wq[0], w1 = wq[1];
                fma2(acc[0], vp, w0.x); fma2(acc[1], vp, w0.y);
                fma2(acc[2], vp, w1.x); fma2(acc[3], vp, w1.y);
            }
        }
        int oy_g = rh * 9 + oy_l;
        int gpos = oy_g * 18 + ox;
        int oc = ocg * 8;
#pragma unroll
        for (int o2 = 0; o2 < 4; o2++) {
            float2 p = upk(acc[o2]);
            g_h2[(b * 32 + oc + o2 * 2) * HW1 + gpos]     = p.x + bias[oc + o2 * 2];
            g_h2[(b * 32 + oc + o2 * 2 + 1) * HW1 + gpos] = p.y + bias[oc + o2 * 2 + 1];
        }
    }
}

// ---------------- K6: fused BN1d + split-K GEMM ----------------
__global__ void k_gemm(const float* __restrict__ fw, const float* __restrict__ bng,
                       const float* __restrict__ bnb) {
    extern __shared__ float sm[];
    float* s_h  = sm;                 // 64 x 132
    float* s_w  = sm + 64 * 132;      // 32 x 128
    float* s_rs = s_w + 4096;
    float* s_rq = s_rs + 256;
    float* s_sc = s_rq + 256;
    float* s_sh = s_sc + 128;
    int f0 = blockIdx.x * 128;
    int tid = threadIdx.x;

    for (int i = tid; i < 8192; i += 256) {
        int bb = i >> 7, k = i & 127;
        int f = f0 + k, c = f / 324;
        s_h[bb * 132 + k] =
            fmaxf(fmaf(g_h2[(size_t)bb * F + f], g_a2[bb * 32 + c], g_b2[bb * 32 + c]), 0.f);
    }
    for (int i = tid; i < 1024; i += 256) {
        int jrow = i >> 5, k4 = i & 31;
        float4 v = *(const float4*)(fw + (size_t)jrow * F + f0 + k4 * 4);
        *(float4*)(s_w + jrow * 128 + k4 * 4) = v;
    }
    __syncthreads();

    {
        int k = tid & 127, half = tid >> 7;
        float s = 0.f, q = 0.f;
#pragma unroll 8
        for (int bb = half * 32; bb < half * 32 + 32; bb++) {
            float v = s_h[bb * 132 + k];
            s += v; q = fmaf(v, v, q);
        }
        s_rs[tid] = s; s_rq[tid] = q;
    }
    __syncthreads();
    if (tid < 128) {
        float S = s_rs[tid] + s_rs[tid + 128];
        float Q = s_rq[tid] + s_rq[tid + 128];
        float mu = S * (1.f / 64.f);
        float var = Q * (1.f / 64.f) - mu * mu;     // biased
        float sc = bng[f0 + tid] * rsqrtf(var + EPSN);
        s_sc[tid] = sc;
        s_sh[tid] = bnb[f0 + tid] - mu * sc;
    }
    __syncthreads();
    for (int i = tid; i < 8192; i += 256) {
        int bb = i >> 7, k = i & 127;
        s_h[bb * 132 + k] = fmaf(s_h[bb * 132 + k], s_sc[k], s_sh[k]);
    }
    __syncthreads();

    int bb = tid & 63, jg = tid >> 6;
    unsigned long long acc2[8];
#pragma unroll
    for (int j = 0; j < 8; j++) acc2[j] = 0ull;
    const float* hp = s_h + bb * 132;
    const float* wp = s_w + jg * 8 * 128;
    for (int k = 0; k < 128; k += 4) {
        ulonglong2 h2 = *(const ulonglong2*)(hp + k);
#pragma unroll
        for (int j = 0; j < 8; j++) {
            ulonglong2 w2 = *(const ulonglong2*)(wp + j * 128 + k);
            fma2(acc2[j], h2.x, w2.x);
            fma2(acc2[j], h2.y, w2.y);
        }
    }
#pragma unroll
    for (int j = 0; j < 8; j++) {
        float2 p = upk(acc2[j]);
        g_part[(size_t)blockIdx.x * 2048 + bb * 32 + jg * 8 + j] = p.x + p.y;
    }
}

// ---------------- K7: reduce partials (float4) + fc relu + heads + softmax ----------------
__global__ void k_heads(const float* __restrict__ fcb,
                        const float* __restrict__ sw, const float* __restrict__ sb,
                        const float* __restrict__ vw, const float* __restrict__ vb,
                        float* __restrict__ out) {
    __shared__ float s_y[2048];
    int tid = threadIdx.x;
    if (tid < 512) {
        float4 acc = make_float4(0.f, 0.f, 0.f, 0.f);
#pragma unroll 8
        for (int p = 0; p < 81; p++) {
            float4 v = ((const float4*)(g_part + (size_t)p * 2048))[tid];
            acc.x += v.x; acc.y += v.y; acc.z += v.z; acc.w += v.w;
        }
        int t = tid * 4;
        s_y[t + 0] = fmaxf(acc.x + fcb[t & 31], 0.f);
        s_y[t + 1] = fmaxf(acc.y + fcb[(t + 1) & 31], 0.f);
        s_y[t + 2] = fmaxf(acc.z + fcb[(t + 2) & 31], 0.f);
        s_y[t + 3] = fmaxf(acc.w + fcb[(t + 3) & 31], 0.f);
    }
    __syncthreads();
    if (tid < 64) {
        int b = tid;
        float h[32];
#pragma unroll
        for (int j = 0; j < 32; j++) h[j] = s_y[b * 32 + j];

        float sl[5];
#pragma unroll
        for (int k = 0; k < 5; k++) {
            float a = sb[k];
            for (int j = 0; j < 32; j++) a = fmaf(h[j], sw[k * 32 + j], a);
            sl[k] = a;
        }
        float mx = sl[0];
#pragma unroll
        for (int k = 1; k < 5; k++) mx = fmaxf(mx, sl[k]);
        float den = 0.f;
#pragma unroll
        for (int k = 0; k < 5; k++) { sl[k] = expf(sl[k] - mx); den += sl[k]; }
        float invd = 1.f / den;
#pragma unroll
        for (int k = 0; k < 5; k++) out[b * 5 + k] = sl[k] * invd;

        float vl[2];
#pragma unroll
        for (int k = 0; k < 2; k++) {
            float a = vb[k];
            for (int j = 0; j < 32; j++) a = fmaf(h[j], vw[k * 32 + j], a);
            vl[k] = a;
        }
        float m2 = fmaxf(vl[0], vl[1]);
        float e0 = expf(vl[0] - m2), e1 = expf(vl[1] - m2);
        float id = 1.f / (e0 + e1);
        out[320 + b * 2 + 0] = e0 * id;
        out[320 + b * 2 + 1] = e1 * id;
    }
}

extern "C" void kernel_launch(void* const* d_in, const int* in_sizes, int n_in,
                              void* d_out, int out_size) {
    const float* x       = (const float*)d_in[0];
    const float* conv0_w = (const float*)d_in[1];
    const float* conv0_b = (const float*)d_in[2];
    const float* conv1_w = (const float*)d_in[3];
    const float* conv1_b = (const float*)d_in[4];
    const float* conv2_w = (const float*)d_in[5];
    const float* conv2_b = (const float*)d_in[6];
    const float* gn0_w   = (const float*)d_in[7];
    const float* gn0_b   = (const float*)d_in[8];
    const float* n1_w    = (const float*)d_in[9];
    const float* n1_b    = (const float*)d_in[10];
    const float* n2_w    = (const float*)d_in[11];
    const float* n2_b    = (const float*)d_in[12];
    const float* bn_g    = (const float*)d_in[13];
    const float* bn_b    = (const float*)d_in[14];
    const float* fc1_w   = (const float*)d_in[15];
    const float* fc1_b   = (const float*)d_in[16];
    const float* shape_w = (const float*)d_in[17];
    const float* shape_b = (const float*)d_in[18];
    const float* vern_w  = (const float*)d_in[19];
    const float* vern_b  = (const float*)d_in[20];
    float* out = (float*)d_out;

    float* h1_p; cudaGetSymbolAddress((void**)&h1_p, g_h1);
    float* h2_p; cudaGetSymbolAddress((void**)&h2_p, g_h2);
    float* a1_p; cudaGetSymbolAddress((void**)&a1_p, g_a1);
    float* b1_p; cudaGetSymbolAddress((void**)&b1_p, g_b1);
    float* a2_p; cudaGetSymbolAddress((void**)&a2_p, g_a2);
    float* b2_p; cudaGetSymbolAddress((void**)&b2_p, g_b2);

    const int smem0 = (23940 + 1176) * 4;
    const int smem1 = (12992 + 3200) * 4;
    const int smem2 = (3520 + 4608) * 4;
    const int smemg = (64 * 132 + 4096 + 256 + 256 + 128 + 128) * 4;
    cudaFuncSetAttribute(k_conv0, cudaFuncAttributeMaxDynamicSharedMemorySize, smem0);
    cudaFuncSetAttribute(k_conv1, cudaFuncAttributeMaxDynamicSharedMemorySize, smem1);
    cudaFuncSetAttribute(k_conv2, cudaFuncAttributeMaxDynamicSharedMemorySize, smem2);
    cudaFuncSetAttribute(k_gemm,  cudaFuncAttributeMaxDynamicSharedMemorySize, smemg);

    k_conv0<<<64 * 7, 224, smem0>>>(x, conv0_w, conv0_b);
    k_conv1<<<128, 672, smem1>>>(conv1_w, conv1_b, gn0_w, gn0_b);
    k_entstats<<<1024, 224>>>(h1_p, a1_p, b1_p, n1_w, n1_b, 15);
    k_conv2<<<128, 672, smem2>>>(conv2_w, conv2_b);
    k_entstats<<<2048, 224>>>(h2_p, a2_p, b2_p, n2_w, n2_b, 31);
    k_gemm<<<81, 256, smemg>>>(fc1_w, bn_g, bn_b);
    k_heads<<<1, 1024>>>(fc1_b, shape_w, shape_b, vern_w, vern_b, out);
}

// round 16
// speedup vs baseline: 1.2789x; 1.0207x over previous
#include <cuda_runtime.h>
#include <math.h>

#define B 64
#define C0 8
#define HW0 3136
#define HW1 324
#define F 10368
#define EPSN 1e-5f

// ---------------- persistent scratch ----------------
__device__ float g_h0[B*C0*HW0];
__device__ float g_ps0[B*7*16];
__device__ float g_h1[B*16*HW1];
__device__ float g_a1[B*16], g_b1[B*16];
__device__ float g_h2[B*32*HW1];
__device__ float g_a2[B*32], g_b2[B*32];
__device__ float g_part[81*B*32];

// ---------------- packed f32x2 helpers (sm_103a FFMA2 path) ----------------
__device__ __forceinline__ unsigned long long pk2(float lo, float hi) {
    unsigned long long r;
    asm("mov.b64 %0, {%1, %2};" : "=l"(r)
        : "r"(__float_as_uint(lo)), "r"(__float_as_uint(hi)));
    return r;
}
__device__ __forceinline__ void fma2(unsigned long long& d,
                                     unsigned long long a, unsigned long long b) {
    asm("fma.rn.f32x2 %0, %1, %2, %0;" : "+l"(d) : "l"(a), "l"(b));
}
__device__ __forceinline__ float2 upk(unsigned long long p) {
    unsigned int lo, hi;
    asm("mov.b64 {%0, %1}, %2;" : "=r"(lo), "=r"(hi) : "l"(p));
    return make_float2(__uint_as_float(lo), __uint_as_float(hi));
}

// ---------------- K1: conv0 7x7 s4 p2 + per-block GroupNorm partials ----------------
// grid 448 = 64b x 7 tiles, block 224.
__global__ void k_conv0(const float* __restrict__ x, const float* __restrict__ w,
                        const float* __restrict__ bias) {
    extern __shared__ float sm[];
    float* s_in = sm;            // 23940
    float* s_w  = sm + 23940;    // 1176
    __shared__ float s_ps[7][16];
    int blk = blockIdx.x;
    int b = blk / 7, tile = blk - b * 7;
    int tid = threadIdx.x;

    for (int i = tid; i < 1176; i += 224) {
        int o = i / 147, rem = i - o * 147;
        s_w[rem * 8 + o] = w[i];
    }
    for (int i = tid; i < 5985; i += 224)
        ((float4*)s_in)[i] = make_float4(0.f, 0.f, 0.f, 0.f);
    __syncthreads();

    const float* xb = x + (size_t)b * 3 * 224 * 224;
    for (int i = tid; i < 5880; i += 224) {
        int ic = i / 1960;
        int rem = i - ic * 1960;
        int r = rem / 56, cch = rem - r * 56;
        int gr = tile * 32 - 2 + r;
        if (gr >= 0 && gr < 224) {
            float4 v = *(const float4*)(xb + (ic * 224 + gr) * 224 + cch * 4);
            float* base = s_in + ((ic * 35 + r) * 4) * 57;
            base[2 * 57 + cch]     = v.x;
            base[3 * 57 + cch]     = v.y;
            base[0 * 57 + cch + 1] = v.z;
            base[1 * 57 + cch + 1] = v.w;
        }
    }
    __syncthreads();

    int r0 = tid / 56, ocol = tid - r0 * 56;
    unsigned long long a0[4], a1[4];
#pragma unroll
    for (int o = 0; o < 4; o++) { a0[o] = 0ull; a1[o] = 0ull; }

#pragma unroll
    for (int ic = 0; ic < 3; ic++)
#pragma unroll
        for (int ky = 0; ky < 7; ky++) {
            int rowbase = (ic * 35 + r0 * 4 + ky) * 4;
            int tap0 = (ic * 49 + ky * 7) * 8;
#pragma unroll
            for (int kx = 0; kx < 7; kx++) {
                int idx = (rowbase + (kx & 3)) * 57 + ocol + (kx >> 2);
                float v0 = s_in[idx];
                float v1 = s_in[idx + 16 * 4 * 57];
                unsigned long long v0p = pk2(v0, v0);
                unsigned long long v1p = pk2(v1, v1);
                const ulonglong2* wq = (const ulonglong2*)(s_w + tap0 + kx * 8);
                ulonglong2 wA = wq[0], wB = wq[1];
                fma2(a0[0], v0p, wA.x); fma2(a0[1], v0p, wA.y);
                fma2(a0[2], v0p, wB.x); fma2(a0[3], v0p, wB.y);
                fma2(a1[0], v1p, wA.x); fma2(a1[1], v1p, wA.y);
                fma2(a1[2], v1p, wB.x); fma2(a1[3], v1p, wB.y);
            }
        }
    int orow0 = tile * 8 + r0;
    float sv[8], sq[8];
#pragma unroll
    for (int o2 = 0; o2 < 4; o2++) {
        float2 p0 = upk(a0[o2]);
        float2 p1 = upk(a1[o2]);
        int o = o2 * 2;
        float bv0 = bias[o], bv1 = bias[o + 1];
        float v00 = p0.x + bv0, v01 = p0.y + bv1;
        float v10 = p1.x + bv0, v11 = p1.y + bv1;
        g_h0[((b * 8 + o) * 56 + orow0) * 56 + ocol]         = v00;
        g_h0[((b * 8 + o + 1) * 56 + orow0) * 56 + ocol]     = v01;
        g_h0[((b * 8 + o) * 56 + orow0 + 4) * 56 + ocol]     = v10;
        g_h0[((b * 8 + o + 1) * 56 + orow0 + 4) * 56 + ocol] = v11;
        sv[o]     = v00 + v10;
        sq[o]     = fmaf(v00, v00, v10 * v10);
        sv[o + 1] = v01 + v11;
        sq[o + 1] = fmaf(v01, v01, v11 * v11);
    }
    int lane = tid & 31, wid = tid >> 5;
#pragma unroll
    for (int o = 0; o < 8; o++) {
        float s = sv[o], q = sq[o];
#pragma unroll
        for (int off = 16; off > 0; off >>= 1) {
            s += __shfl_xor_sync(0xffffffffu, s, off);
            q += __shfl_xor_sync(0xffffffffu, q, off);
        }
        if (lane == 0) { s_ps[wid][o * 2] = s; s_ps[wid][o * 2 + 1] = q; }
    }
    __syncthreads();
    if (tid < 16) {
        float acc = 0.f;
#pragma unroll
        for (int wI = 0; wI < 7; wI++) acc += s_ps[wI][tid];
        g_ps0[(b * 7 + tile) * 16 + tid] = acc;
    }
}

// ---------------- K2: conv1 5x5 s3 p1, (batch, 9-row half, 16 oc), 672 thr ----------------
__global__ void __launch_bounds__(672) k_conv1(const float* __restrict__ w,
                                               const float* __restrict__ bias,
                                               const float* __restrict__ gw,
                                               const float* __restrict__ gb) {
    extern __shared__ float sm[];
    float* s_in = sm;            // 12992
    float* s_w  = sm + 12992;    // 3200
    __shared__ float s_a[8], s_b[8];
    int b = blockIdx.x >> 1, rh = blockIdx.x & 1;
    int tid = threadIdx.x;

    for (int i = tid; i < 3200; i += 672) {
        int o = i / 200, rem = i - o * 200;
        s_w[rem * 16 + o] = w[i];
    }
    if (tid < 8) {
        float S = 0.f, Q = 0.f;
#pragma unroll
        for (int t = 0; t < 7; t++) {
            S += g_ps0[(b * 7 + t) * 16 + tid * 2];
            Q += g_ps0[(b * 7 + t) * 16 + tid * 2 + 1];
        }
        float mu = S * (1.f / 3136.f);
        float var = Q * (1.f / 3136.f) - mu * mu;   // biased
        float a = rsqrtf(var + EPSN) * gw[tid];
        s_a[tid] = a;
        s_b[tid] = gb[tid] - mu * a;
    }
    __syncthreads();

    int rowbase = 27 * rh - 1;
    const float* h0b = g_h0 + (size_t)b * 8 * HW0;
    for (int i = tid; i < 12992; i += 672) {
        int ic = i / 1624;
        int rem = i - ic * 1624;
        int r = rem / 56, cc = rem - r * 56;
        int grow = rowbase + r, gcol = cc - 1;
        float v = 0.f;
        if (grow >= 0 && gcol >= 0)
            v = fmaxf(fmaf(h0b[ic * 3136 + grow * 56 + gcol], s_a[ic], s_b[ic]), 0.f);
        s_in[i] = v;
    }
    __syncthreads();

    if (tid < 648) {
        int pos = tid % 162, ocg = tid / 162;
        int oy_l = pos / 18, ox = pos - oy_l * 18;
        unsigned long long acc[2] = {0ull, 0ull};
#pragma unroll 2
        for (int ic = 0; ic < 8; ic++) {
#pragma unroll
            for (int ky = 0; ky < 5; ky++) {
                const float* ip = s_in + (ic * 29 + oy_l * 3 + ky) * 56 + ox * 3;
                float v0 = ip[0], v1 = ip[1], v2 = ip[2], v3 = ip[3], v4 = ip[4];
                const float* wp = s_w + (ic * 25 + ky * 5) * 16 + ocg * 4;
                ulonglong2 w0 = *(const ulonglong2*)(wp);
                ulonglong2 w1 = *(const ulonglong2*)(wp + 16);
                ulonglong2 w2 = *(const ulonglong2*)(wp + 32);
                ulonglong2 w3 = *(const ulonglong2*)(wp + 48);
                ulonglong2 w4 = *(const ulonglong2*)(wp + 64);
                unsigned long long p0 = pk2(v0, v0), p1 = pk2(v1, v1), p2 = pk2(v2, v2);
                unsigned long long p3 = pk2(v3, v3), p4 = pk2(v4, v4);
                fma2(acc[0], p0, w0.x); fma2(acc[1], p0, w0.y);
                fma2(acc[0], p1, w1.x); fma2(acc[1], p1, w1.y);
                fma2(acc[0], p2, w2.x); fma2(acc[1], p2, w2.y);
                fma2(acc[0], p3, w3.x); fma2(acc[1], p3, w3.y);
                fma2(acc[0], p4, w4.x); fma2(acc[1], p4, w4.y);
            }
        }
        int oy_g = rh * 9 + oy_l;
        int gpos = oy_g * 18 + ox;
        int oc = ocg * 4;
        float2 pA = upk(acc[0]), pB = upk(acc[1]);
        g_h1[(b * 16 + oc + 0) * HW1 + gpos] = pA.x + bias[oc + 0];
        g_h1[(b * 16 + oc + 1) * HW1 + gpos] = pA.y + bias[oc + 1];
        g_h1[(b * 16 + oc + 2) * HW1 + gpos] = pB.x + bias[oc + 2];
        g_h1[(b * 16 + oc + 3) * HW1 + gpos] = pB.y + bias[oc + 3];
    }
}

// ---------------- K3/K5: entropy + instance-norm stats per (b,c), 224 thr ----------------
__global__ void __launch_bounds__(224) k_entstats(const float* __restrict__ src,
                                                  float* __restrict__ ga, float* __restrict__ gb,
                                                  const float* __restrict__ nw,
                                                  const float* __restrict__ nb, int Cmask) {
    __shared__ float s_ch[324];
    __shared__ float sred[24];
    int bc = blockIdx.x, c = bc & Cmask;
    int tid = threadIdx.x;
    int lane = tid & 31, wid = tid >> 5;

    float lutv = 0.f;
    {
        int li = lane < 26 ? lane : 25;
        float pk = __fdiv_rn((float)li, 25.0f);
        float pc = fminf(fmaxf(pk, 1e-5f), 1.0f - 1e-5f);
        lutv = -pk * logf(pc);
    }

    float s = 0.f, q = 0.f;
    if (tid < 81) {
        float4 v4 = ((const float4*)(src + (size_t)bc * 324))[tid];
        ((float4*)s_ch)[tid] = v4;
        s = v4.x + v4.y + v4.z + v4.w;
        q = fmaf(v4.x, v4.x, fmaf(v4.y, v4.y, fmaf(v4.z, v4.z, v4.w * v4.w)));
    }
    __syncthreads();

    float ep;
    {
        int pidx = tid < 196 ? tid : 195;
        int py = pidx / 14, px = pidx - py * 14;
        const float* pbase = s_ch + py * 18 + px;
        float v[25];
#pragma unroll
        for (int dy = 0; dy < 5; dy++)
#pragma unroll
            for (int dx = 0; dx < 5; dx++)
                v[dy * 5 + dx] = pbase[dy * 18 + dx];
        float mn8[8], mx8[8];
#pragma unroll
        for (int i = 0; i < 8; i++) {
            float a2 = fminf(v[3 * i], v[3 * i + 1]);
            float b2 = fmaxf(v[3 * i], v[3 * i + 1]);
            mn8[i] = fminf(a2, v[3 * i + 2]);
            mx8[i] = fmaxf(b2, v[3 * i + 2]);
        }
        float mn4a = fminf(fminf(mn8[0], mn8[1]), fminf(mn8[2], mn8[3]));
        float mn4b = fminf(fminf(mn8[4], mn8[5]), fminf(mn8[6], mn8[7]));
        float mx4a = fmaxf(fmaxf(mx8[0], mx8[1]), fmaxf(mx8[2], mx8[3]));
        float mx4b = fmaxf(fmaxf(mx8[4], mx8[5]), fmaxf(mx8[6], mx8[7]));
        float mn = fminf(fminf(mn4a, mn4b), v[24]);
        float mx = fmaxf(fmaxf(mx4a, mx4b), v[24]);

        float rng = (mx > mn) ? (mx - mn) : 1.0f;
        float s25 = __frcp_rn(rng) * 25.0f;
        float ms  = -mn * s25;
        unsigned long long lo0 = 0ull, lo1 = 0ull, hi0 = 0ull, hi1 = 0ull;
        int c24 = 0;
#pragma unroll
        for (int i = 0; i < 25; i++) {
            float t = fmaf(v[i], s25, ms);
            int bi = (int)t;
            bi = bi > 24 ? 24 : bi;
            unsigned long long inc;
            if (bi < 12) {
                inc = 1ull << (bi * 5);
                if (i & 1) lo1 += inc; else lo0 += inc;
            } else if (bi < 24) {
                inc = 1ull << ((bi - 12) * 5);
                if (i & 1) hi1 += inc; else hi0 += inc;
            } else c24++;
        }
        unsigned long long lo = lo0 + lo1, hi = hi0 + hi1;
        ep = 0.f;
#pragma unroll
        for (int k = 0; k < 12; k++) {
            int idx = (int)((lo >> (k * 5)) & 31u);
            ep += __shfl_sync(0xffffffffu, lutv, idx);
        }
#pragma unroll
        for (int k = 0; k < 12; k++) {
            int idx = (int)((hi >> (k * 5)) & 31u);
            ep += __shfl_sync(0xffffffffu, lutv, idx);
        }
        ep += __shfl_sync(0xffffffffu, lutv, c24);
        if (tid >= 196) ep = 0.f;
    }

#pragma unroll
    for (int o = 16; o > 0; o >>= 1) {
        s  += __shfl_xor_sync(0xffffffffu, s, o);
        q  += __shfl_xor_sync(0xffffffffu, q, o);
        ep += __shfl_xor_sync(0xffffffffu, ep, o);
    }
    if (lane == 0) { sred[wid] = s; sred[wid + 8] = q; sred[wid + 16] = ep; }
    __syncthreads();
    if (tid == 0) {
        float S = 0.f, Q = 0.f, E = 0.f;
        for (int wI = 0; wI < 7; wI++) { S += sred[wI]; Q += sred[wI + 8]; E += sred[wI + 16]; }
        float ent = E * (1.0f / 196.0f);
        float mu = S * (1.0f / 324.0f);
        float var = (Q * (1.0f / 324.0f) - mu * mu) * (324.0f / 323.0f);
        float a = rsqrtf(var + EPSN) * nw[c] * ent;
        ga[bc] = a;
        gb[bc] = nb[c] - mu * a;
    }
}

// ---------------- K4: conv2 3x3 s1 p1, (batch, 9-row half, 32 oc), 672 thr ----------------
__global__ void __launch_bounds__(672) k_conv2(const float* __restrict__ w,
                                               const float* __restrict__ bias) {
    extern __shared__ float sm[];
    float* s_in = sm;            // 3520
    float* s_w  = sm + 3520;     // 4608
    __shared__ float s_a[16], s_b[16];
    int b = blockIdx.x >> 1, rh = blockIdx.x & 1;
    int tid = threadIdx.x;

    if (tid < 16) { s_a[tid] = g_a1[b * 16 + tid]; s_b[tid] = g_b1[b * 16 + tid]; }
    for (int i = tid; i < 4608; i += 672) {
        int o = i / 144, rem = i - o * 144;
        s_w[rem * 32 + o] = w[i];
    }
    __syncthreads();

    int rowbase = rh * 9 - 1;
    for (int i = tid; i < 3520; i += 672) {
        int ic = i / 220;
        int rem = i - ic * 220;
        int r = rem / 20, cc = rem - r * 20;
        int grow = rowbase + r, gcol = cc - 1;
        float v = 0.f;
        if (grow >= 0 && grow < 18 && gcol >= 0 && gcol < 18)
            v = fmaxf(fmaf(g_h1[(b * 16 + ic) * 324 + grow * 18 + gcol], s_a[ic], s_b[ic]), 0.f);
        s_in[i] = v;
    }
    __syncthreads();

    if (tid < 648) {
        int pos = tid % 162, ocg = tid / 162;
        int oy_l = pos / 18, ox = pos - oy_l * 18;
        unsigned long long acc[4] = {0ull, 0ull, 0ull, 0ull};
#pragma unroll 2
        for (int ic = 0; ic < 16; ic++) {
            const float* rp = s_in + (ic * 11 + oy_l) * 20 + ox;
            float i00 = rp[0],  i01 = rp[1],  i02 = rp[2];
            float i10 = rp[20], i11 = rp[21], i12 = rp[22];
            float i20 = rp[40], i21 = rp[41], i22 = rp[42];
            const float* wp = s_w + ic * 9 * 32 + ocg * 8;
            float iv[9] = {i00, i01, i02, i10, i11, i12, i20, i21, i22};
#pragma unroll
            for (int t = 0; t < 9; t++) {
                unsigned long long vp = pk2(iv[t], iv[t]);
                const ulonglong2* wq = (const ulonglong2*)(wp + t * 32);
                ulonglong2 w0 = wq[0], w1 = wq[1];
                fma2(acc[0], vp, w0.x); fma2(acc[1], vp, w0.y);
                fma2(acc[2], vp, w1.x); fma2(acc[3], vp, w1.y);
            }
        }
        int oy_g = rh * 9 + oy_l;
        int gpos = oy_g * 18 + ox;
        int oc = ocg * 8;
#pragma unroll
        for (int o2 = 0; o2 < 4; o2++) {
            float2 p = upk(acc[o2]);
            g_h2[(b * 32 + oc + o2 * 2) * HW1 + gpos]     = p.x + bias[oc + o2 * 2];
            g_h2[(b * 32 + oc + o2 * 2 + 1) * HW1 + gpos] = p.y + bias[oc + o2 * 2 + 1];
        }
    }
}

// ---------------- K6: fused BN1d + split-K GEMM ----------------
__global__ void k_gemm(const float* __restrict__ fw, const float* __restrict__ bng,
                       const float* __restrict__ bnb) {
    extern __shared__ float sm[];
    float* s_h  = sm;                 // 64 x 132
    float* s_w  = sm + 64 * 132;      // 32 x 128
    float* s_rs = s_w + 4096;
    float* s_rq = s_rs + 256;
    float* s_sc = s_rq + 256;
    float* s_sh = s_sc + 128;
    int f0 = blockIdx.x * 128;
    int tid = threadIdx.x;

    for (int i = tid; i < 8192; i += 256) {
        int bb = i >> 7, k = i & 127;
        int f = f0 + k, c = f / 324;
        s_h[bb * 132 + k] =
            fmaxf(fmaf(g_h2[(size_t)bb * F + f], g_a2[bb * 32 + c], g_b2[bb * 32 + c]), 0.f);
    }
    for (int i = tid; i < 1024; i += 256) {
        int jrow = i >> 5, k4 = i & 31;
        float4 v = *(const float4*)(fw + (size_t)jrow * F + f0 + k4 * 4);
        *(float4*)(s_w + jrow * 128 + k4 * 4) = v;
    }
    __syncthreads();

    {
        int k = tid & 127, half = tid >> 7;
        float s = 0.f, q = 0.f;
#pragma unroll 8
        for (int bb = half * 32; bb < half * 32 + 32; bb++) {
            float v = s_h[bb * 132 + k];
            s += v; q = fmaf(v, v, q);
        }
        s_rs[tid] = s; s_rq[tid] = q;
    }
    __syncthreads();
    if (tid < 128) {
        float S = s_rs[tid] + s_rs[tid + 128];
        float Q = s_rq[tid] + s_rq[tid + 128];
        float mu = S * (1.f / 64.f);
        float var = Q * (1.f / 64.f) - mu * mu;     // biased
        float sc = bng[f0 + tid] * rsqrtf(var + EPSN);
        s_sc[tid] = sc;
        s_sh[tid] = bnb[f0 + tid] - mu * sc;
    }
    __syncthreads();
    for (int i = tid; i < 8192; i += 256) {
        int bb = i >> 7, k = i & 127;
        s_h[bb * 132 + k] = fmaf(s_h[bb * 132 + k], s_sc[k], s_sh[k]);
    }
    __syncthreads();

    int bb = tid & 63, jg = tid >> 6;
    unsigned long long acc2[8];
#pragma unroll
    for (int j = 0; j < 8; j++) acc2[j] = 0ull;
    const float* hp = s_h + bb * 132;
    const float* wp = s_w + jg * 8 * 128;
    for (int k = 0; k < 128; k += 4) {
        ulonglong2 h2 = *(const ulonglong2*)(hp + k);
#pragma unroll
        for (int j = 0; j < 8; j++) {
            ulonglong2 w2 = *(const ulonglong2*)(wp + j * 128 + k);
            fma2(acc2[j], h2.x, w2.x);
            fma2(acc2[j], h2.y, w2.y);
        }
    }
#pragma unroll
    for (int j = 0; j < 8; j++) {
        float2 p = upk(acc2[j]);
        g_part[(size_t)blockIdx.x * 2048 + bb * 32 + jg * 8 + j] = p.x + p.y;
    }
}

// ---------------- K7: split partial reduce + fc relu + heads + softmax ----------------
__global__ void k_heads(const float* __restrict__ fcb,
                        const float* __restrict__ sw, const float* __restrict__ sb,
                        const float* __restrict__ vw, const float* __restrict__ vb,
                        float* __restrict__ out) {
    __shared__ float s_y[2048];
    __shared__ float s_p2[2048];
    int tid = threadIdx.x;
    // split the 81-partial reduction across two 512-thread groups
    {
        int grp = tid >> 9;              // 0 or 1
        int t4  = tid & 511;             // float4 index
        int p0g = grp ? 41 : 0;
        int p1g = grp ? 81 : 41;
        float4 acc = make_float4(0.f, 0.f, 0.f, 0.f);
#pragma unroll 8
        for (int p = p0g; p < p1g; p++) {
            float4 v = ((const float4*)(g_part + (size_t)p * 2048))[t4];
            acc.x += v.x; acc.y += v.y; acc.z += v.z; acc.w += v.w;
        }
        if (grp) {
            ((float4*)s_p2)[t4] = acc;
        } else {
            ((float4*)s_y)[t4] = acc;
        }
    }
    __syncthreads();
    if (tid < 512) {
        float4 a = ((float4*)s_y)[tid];
        float4 bq = ((float4*)s_p2)[tid];
        int t = tid * 4;
        s_y[t + 0] = fmaxf(a.x + bq.x + fcb[t & 31], 0.f);
        s_y[t + 1] = fmaxf(a.y + bq.y + fcb[(t + 1) & 31], 0.f);
        s_y[t + 2] = fmaxf(a.z + bq.z + fcb[(t + 2) & 31], 0.f);
        s_y[t + 3] = fmaxf(a.w + bq.w + fcb[(t + 3) & 31], 0.f);
    }
    __syncthreads();
    if (tid < 64) {
        int b = tid;
        float h[32];
#pragma unroll
        for (int j = 0; j < 32; j++) h[j] = s_y[b * 32 + j];

        float sl[5];
#pragma unroll
        for (int k = 0; k < 5; k++) {
            float a = sb[k];
            for (int j = 0; j < 32; j++) a = fmaf(h[j], sw[k * 32 + j], a);
            sl[k] = a;
        }
        float mx = sl[0];
#pragma unroll
        for (int k = 1; k < 5; k++) mx = fmaxf(mx, sl[k]);
        float den = 0.f;
#pragma unroll
        for (int k = 0; k < 5; k++) { sl[k] = expf(sl[k] - mx); den += sl[k]; }
        float invd = 1.f / den;
#pragma unroll
        for (int k = 0; k < 5; k++) out[b * 5 + k] = sl[k] * invd;

        float vl[2];
#pragma unroll
        for (int k = 0; k < 2; k++) {
            float a = vb[k];
            for (int j = 0; j < 32; j++) a = fmaf(h[j], vw[k * 32 + j], a);
            vl[k] = a;
        }
        float m2 = fmaxf(vl[0], vl[1]);
        float e0 = expf(vl[0] - m2), e1 = expf(vl[1] - m2);
        float id = 1.f / (e0 + e1);
        out[320 + b * 2 + 0] = e0 * id;
        out[320 + b * 2 + 1] = e1 * id;
    }
}

extern "C" void kernel_launch(void* const* d_in, const int* in_sizes, int n_in,
                              void* d_out, int out_size) {
    const float* x       = (const float*)d_in[0];
    const float* conv0_w = (const float*)d_in[1];
    const float* conv0_b = (const float*)d_in[2];
    const float* conv1_w = (const float*)d_in[3];
    const float* conv1_b = (const float*)d_in[4];
    const float* conv2_w = (const float*)d_in[5];
    const float* conv2_b = (const float*)d_in[6];
    const float* gn0_w   = (const float*)d_in[7];
    const float* gn0_b   = (const float*)d_in[8];
    const float* n1_w    = (const float*)d_in[9];
    const float* n1_b    = (const float*)d_in[10];
    const float* n2_w    = (const float*)d_in[11];
    const float* n2_b    = (const float*)d_in[12];
    const float* bn_g    = (const float*)d_in[13];
    const float* bn_b    = (const float*)d_in[14];
    const float* fc1_w   = (const float*)d_in[15];
    const float* fc1_b   = (const float*)d_in[16];
    const float* shape_w = (const float*)d_in[17];
    const float* shape_b = (const float*)d_in[18];
    const float* vern_w  = (const float*)d_in[19];
    const float* vern_b  = (const float*)d_in[20];
    float* out = (float*)d_out;

    float* h1_p; cudaGetSymbolAddress((void**)&h1_p, g_h1);
    float* h2_p; cudaGetSymbolAddress((void**)&h2_p, g_h2);
    float* a1_p; cudaGetSymbolAddress((void**)&a1_p, g_a1);
    float* b1_p; cudaGetSymbolAddress((void**)&b1_p, g_b1);
    float* a2_p; cudaGetSymbolAddress((void**)&a2_p, g_a2);
    float* b2_p; cudaGetSymbolAddress((void**)&b2_p, g_b2);

    const int smem0 = (23940 + 1176) * 4;
    const int smem1 = (12992 + 3200) * 4;
    const int smem2 = (3520 + 4608) * 4;
    const int smemg = (64 * 132 + 4096 + 256 + 256 + 128 + 128) * 4;
    cudaFuncSetAttribute(k_conv0, cudaFuncAttributeMaxDynamicSharedMemorySize, smem0);
    cudaFuncSetAttribute(k_conv1, cudaFuncAttributeMaxDynamicSharedMemorySize, smem1);
    cudaFuncSetAttribute(k_conv2, cudaFuncAttributeMaxDynamicSharedMemorySize, smem2);
    cudaFuncSetAttribute(k_gemm,  cudaFuncAttributeMaxDynamicSharedMemorySize, smemg);

    k_conv0<<<64 * 7, 224, smem0>>>(x, conv0_w, conv0_b);
    k_conv1<<<128, 672, smem1>>>(conv1_w, conv1_b, gn0_w, gn0_b);
    k_entstats<<<1024, 224>>>(h1_p, a1_p, b1_p, n1_w, n1_b, 15);
    k_conv2<<<128, 672, smem2>>>(conv2_w, conv2_b);
    k_entstats<<<2048, 224>>>(h2_p, a2_p, b2_p, n2_w, n2_b, 31);
    k_gemm<<<81, 256, smemg>>>(fc1_w, bn_g, bn_b);
    k_heads<<<1, 1024>>>(fc1_b, shape_w, shape_b, vern_w, vern_b, out);
}